// round 1
// baseline (speedup 1.0000x reference)
#include <cuda_runtime.h>
#include <cuda_bf16.h>
#include <stdint.h>

// Output collapses analytically: alpha[e] = 1 / (#edges sharing dst[e]) per
// relation, because the edge softmax is over identical per-dst logits
// (e - emax == 0 exactly -> ex == 1 -> denom == in-degree count).
// So: histogram dst, then out = 1/deg[dst]. All GEMM/elu/attn work is dead.

#define MAXN 131072          // >= N (100000), power-of-2 padded scratch

__device__ int g_deg[2 * MAXN];   // [0:MAXN) = relation ui, [MAXN:2*MAXN) = iu

__global__ void zero_deg_kernel(int n2)
{
    int i = blockIdx.x * blockDim.x + threadIdx.x;
    if (i < n2) g_deg[i] = 0;
}

__global__ void hist_kernel(const int* __restrict__ dst_ui,
                            const int* __restrict__ dst_iu,
                            int E)
{
    int i = blockIdx.x * blockDim.x + threadIdx.x;
    if (i < E) {
        atomicAdd(&g_deg[dst_ui[i]], 1);
    } else if (i < 2 * E) {
        atomicAdd(&g_deg[MAXN + dst_iu[i - E]], 1);
    }
}

__global__ void alpha_kernel(const int* __restrict__ dst_ui,
                             const int* __restrict__ dst_iu,
                             float* __restrict__ out,
                             int E)
{
    int i = blockIdx.x * blockDim.x + threadIdx.x;
    if (i < E) {
        out[i] = 1.0f / (float)g_deg[dst_ui[i]];
    } else if (i < 2 * E) {
        out[i] = 1.0f / (float)g_deg[MAXN + dst_iu[i - E]];
    }
}

extern "C" void kernel_launch(void* const* d_in, const int* in_sizes, int n_in,
                              void* d_out, int out_size)
{
    // metadata order: 0 h_user, 1 h_item, 2 Wl_user, 3 bl_user, 4 Wl_item,
    // 5 bl_item, 6 Wr_user, 7 br_user, 8 Wr_item, 9 br_item, 10 attn_w,
    // 11 src_ui, 12 dst_ui, 13 src_iu, 14 dst_iu
    const int* dst_ui = (const int*)d_in[12];
    const int* dst_iu = (const int*)d_in[14];
    float* out = (float*)d_out;

    const int E = in_sizes[12];      // 1,000,000 edges per relation
    const int n2 = 2 * MAXN;

    const int TB = 256;
    zero_deg_kernel<<<(n2 + TB - 1) / TB, TB>>>(n2);
    hist_kernel<<<(2 * E + TB - 1) / TB, TB>>>(dst_ui, dst_iu, E);
    alpha_kernel<<<(2 * E + TB - 1) / TB, TB>>>(dst_ui, dst_iu, out, E);
}